// round 9
// baseline (speedup 1.0000x reference)
#include <cuda_runtime.h>
#include <cuda_fp16.h>
#include <cuda.h>
#include <cstdint>

// ---------------- problem constants ----------------
#define B_    16
#define T_    128
#define H_    512
#define L_    2
#define V_    32000
#define M_    (B_ * T_)        // 2048
#define G4_   (4 * H_)         // 2048

// ---------------- GEMM tiling ----------------
#define BM_   128
#define BN_   128
#define BK_   64               // fp16 = 128 bytes/row = SW128 atom
#define KT_   (H_ / BK_)       // 8 k-tiles
#define NSTG  3
#define ST_A  (BM_ * BK_ * 2)  // 16384
#define ST_B  (BN_ * BK_ * 2)  // 16384
#define ST_BYTES (ST_A + ST_B) // 32768
#define SM0   1024
#define SMEM_TOTAL (SM0 + NSTG * ST_BYTES)   // 99328 -> 2 CTAs/SM
#define NTHR  256              // 8 warps: 4 m-warps x 2 n-warps, warp tile 32x64
#define NWARP (NTHR / 32)

// h-tile staging: 128 rows x 32 half, row stride 40 half (80B, conflict-free)
#define HROW  40

// ---------------- scratch (static device globals) ----------------
__device__ __align__(128) __half g_A0[(size_t)M_ * H_];    // activations ping
__device__ __align__(128) __half g_A1[(size_t)M_ * H_];    // activations pong
__device__ __align__(128) __half g_Whf[(size_t)G4_ * H_];  // fp16 W_ih (permuted)
__device__ __align__(128) __half g_Wout[(size_t)V_ * H_];  // fp16 W_out
__device__ float g_hb[B_ * G4_];                           // permuted recurrent contribution
__device__ float g_dummy[2 * L_ * B_ * H_];

__device__ __forceinline__ float sigf(float x) { return 1.0f / (1.0f + expf(-x)); }

// ---------------- PTX helpers (base ISA only; no tcgen05 on sm_103 target) ----
__device__ __forceinline__ uint32_t smem_u32(const void* p) {
    uint32_t a;
    asm("{ .reg .u64 t; cvta.to.shared.u64 t, %1; cvt.u32.u64 %0, t; }" : "=r"(a) : "l"(p));
    return a;
}
__device__ __forceinline__ bool elect1() {
    uint32_t p;
    asm volatile("{ .reg .pred p; elect.sync _|p, 0xFFFFFFFF; selp.b32 %0, 1, 0, p; }" : "=r"(p));
    return p != 0;
}
__device__ __forceinline__ void mbar_init(uint32_t a, uint32_t c) {
    asm volatile("mbarrier.init.shared.b64 [%0], %1;" :: "r"(a), "r"(c) : "memory");
}
__device__ __forceinline__ void mbar_arrive(uint32_t a) {
    asm volatile("mbarrier.arrive.shared.b64 _, [%0];" :: "r"(a) : "memory");
}
__device__ __forceinline__ void mbar_expect_tx(uint32_t a, uint32_t b) {
    asm volatile("mbarrier.arrive.expect_tx.shared.b64 _, [%0], %1;" :: "r"(a), "r"(b) : "memory");
}
__device__ __forceinline__ void mbar_wait(uint32_t a, uint32_t ph) {
    asm volatile(
        "{ .reg .pred P;\n"
        "WL_%=: mbarrier.try_wait.parity.acquire.cta.shared::cta.b64 P, [%0], %1, 0x989680;\n"
        "@P bra.uni WD_%=;\n"
        "bra.uni WL_%=;\n"
        "WD_%=: }" :: "r"(a), "r"(ph) : "memory");
}
__device__ __forceinline__ void tma2d(uint32_t dst, const CUtensorMap* m, int x, int y, uint32_t mbar) {
    asm volatile(
        "cp.async.bulk.tensor.2d.shared::cta.global.tile.mbarrier::complete_tx::bytes "
        "[%0], [%1, {%2, %3}], [%4];"
        :: "r"(dst), "l"(m), "r"(x), "r"(y), "r"(mbar) : "memory");
}
__device__ __forceinline__ void ldsm4(uint32_t& r0, uint32_t& r1, uint32_t& r2, uint32_t& r3,
                                      uint32_t addr) {
    asm volatile("ldmatrix.sync.aligned.m8n8.x4.shared.b16 {%0,%1,%2,%3}, [%4];"
                 : "=r"(r0), "=r"(r1), "=r"(r2), "=r"(r3) : "r"(addr));
}
__device__ __forceinline__ void mma16816(float* c, const uint32_t* a, uint32_t b0, uint32_t b1) {
    asm volatile(
        "mma.sync.aligned.m16n8k16.row.col.f32.f16.f16.f32 "
        "{%0,%1,%2,%3}, {%4,%5,%6,%7}, {%8,%9}, {%0,%1,%2,%3};"
        : "+f"(c[0]), "+f"(c[1]), "+f"(c[2]), "+f"(c[3])
        : "r"(a[0]), "r"(a[1]), "r"(a[2]), "r"(a[3]), "r"(b0), "r"(b1));
}

// ---------------------------------------------------------------------------
// fp16 GEMM with two epilogue modes:
//   mode 0: C[m,n] = acc + bias[n]            (fp32 output, logits)
//   mode 1: fused LSTM cell on permuted-gate columns; h staged through smem
//           (conflict-free stride) then written coalesced into Aout.
// CTA tile 128x128, 256 threads (8 warps, 4m x 2n, warp tile 32x64),
// 2 CTAs/SM, async mbarrier pipeline (no __syncthreads in mainloop).
// ---------------------------------------------------------------------------
__global__ __launch_bounds__(NTHR, 2)
void gemm_f16(const __grid_constant__ CUtensorMap mapA,
              const __grid_constant__ CUtensorMap mapB,
              float* __restrict__ C, int ldc,
              const float* __restrict__ bias,
              int mode,
              const float* __restrict__ hb,
              const float* __restrict__ c0in,
              __half* __restrict__ Aout,
              float* __restrict__ outh,
              float* __restrict__ outc) {
    extern __shared__ __align__(1024) char smem[];
    const uint32_t sb = smem_u32(smem);
    const int tid = threadIdx.x, wid = tid >> 5, lane = tid & 31;
    const int m0 = blockIdx.x * BM_;
    const int n0 = blockIdx.y * BN_;
    const int wm = (wid & 3) * 32;        // warp m offset in CTA tile
    const int wn = (wid >> 2) * 64;       // warp n offset in CTA tile

    const uint32_t FULL  = sb;                // NSTG x 8B
    const uint32_t EMPTY = sb + 8 * NSTG;     // NSTG x 8B

    if (tid == 0) {
        #pragma unroll
        for (int s = 0; s < NSTG; ++s) {
            mbar_init(FULL + 8 * s, 1);
            mbar_init(EMPTY + 8 * s, NWARP);
        }
    }
    __syncthreads();

    if (tid == 0) {
        #pragma unroll
        for (int s = 0; s < NSTG; ++s) {
            mbar_expect_tx(FULL + 8 * s, ST_BYTES);
            uint32_t sa = sb + SM0 + s * ST_BYTES;
            tma2d(sa,        &mapA, s * BK_, m0, FULL + 8 * s);
            tma2d(sa + ST_A, &mapB, s * BK_, n0, FULL + 8 * s);
        }
    }

    float c[2][8][4];
    #pragma unroll
    for (int mi = 0; mi < 2; ++mi)
        #pragma unroll
        for (int nj = 0; nj < 8; ++nj)
            #pragma unroll
            for (int q = 0; q < 4; ++q) c[mi][nj][q] = 0.f;

    const int lr = lane & 15;     // ldmatrix row within 16
    const int hi = lane >> 4;     // ldmatrix k-chunk select

    uint32_t offA[2], offB[4];
    #pragma unroll
    for (int mi = 0; mi < 2; ++mi) {
        int r = wm + mi * 16 + lr;
        offA[mi] = (uint32_t)(r * 128 + ((hi ^ (r & 7)) << 4));
    }
    #pragma unroll
    for (int nj = 0; nj < 4; ++nj) {
        int r = wn + nj * 16 + lr;
        offB[nj] = (uint32_t)(ST_A + r * 128 + ((hi ^ (r & 7)) << 4));
    }

    const bool producer = (wid == 0) && elect1();

    for (int kt = 0; kt < KT_; ++kt) {
        const int s = kt % NSTG;
        mbar_wait(FULL + 8 * s, (kt / NSTG) & 1);
        const uint32_t sa = sb + SM0 + s * ST_BYTES;

        #pragma unroll
        for (int kk = 0; kk < 4; ++kk) {
            const uint32_t kx = (uint32_t)(kk << 5);
            uint32_t am[2][4], bt[4][4];
            #pragma unroll
            for (int mi = 0; mi < 2; ++mi)
                ldsm4(am[mi][0], am[mi][1], am[mi][2], am[mi][3], sa + (offA[mi] ^ kx));
            #pragma unroll
            for (int nj = 0; nj < 4; ++nj)
                ldsm4(bt[nj][0], bt[nj][1], bt[nj][2], bt[nj][3], sa + (offB[nj] ^ kx));
            #pragma unroll
            for (int mi = 0; mi < 2; ++mi)
                #pragma unroll
                for (int n8 = 0; n8 < 8; ++n8)
                    mma16816(c[mi][n8], am[mi],
                             bt[n8 >> 1][n8 & 1], bt[n8 >> 1][(n8 & 1) + 2]);
        }

        if (lane == 0) mbar_arrive(EMPTY + 8 * s);

        if (producer && kt + NSTG < KT_) {
            mbar_wait(EMPTY + 8 * s, (kt / NSTG) & 1);
            mbar_expect_tx(FULL + 8 * s, ST_BYTES);
            uint32_t sn = sb + SM0 + s * ST_BYTES;
            tma2d(sn,        &mapA, (kt + NSTG) * BK_, m0, FULL + 8 * s);
            tma2d(sn + ST_A, &mapB, (kt + NSTG) * BK_, n0, FULL + 8 * s);
        }
    }

    const int r4 = lane >> 2;            // accum row within 8
    const int c2 = (lane & 3) << 1;      // accum col pair

    if (mode == 0) {
        // -------- logits epilogue: direct register -> global stores --------
        #pragma unroll
        for (int mi = 0; mi < 2; ++mi) {
            int row0 = m0 + wm + mi * 16 + r4;
            #pragma unroll
            for (int n8 = 0; n8 < 8; ++n8) {
                int col = n0 + wn + n8 * 8 + c2;
                float bx = bias[col], by = bias[col + 1];
                float2 v0 = { c[mi][n8][0] + bx, c[mi][n8][1] + by };
                float2 v1 = { c[mi][n8][2] + bx, c[mi][n8][3] + by };
                *reinterpret_cast<float2*>(C + (size_t)row0 * ldc + col) = v0;
                *reinterpret_cast<float2*>(C + (size_t)(row0 + 8) * ldc + col) = v1;
            }
        }
    } else {
        // -------- fused LSTM epilogue, smem-staged coalesced writes --------
        // Even lanes hold (i,f) of their col-quad; odd lanes hold (g,o).
        // shfl_xor(1) swaps; even lane computes local row0, odd lane row0+8.
        const int b = m0 >> 7;            // BM_ == T_ so batch fixed per CTA
        const bool odd = lane & 1;
        __syncthreads();                  // all warps done with pipeline smem
        #pragma unroll
        for (int mi = 0; mi < 2; ++mi) {
            int row0 = wm + mi * 16 + r4;           // local row
            int myrow = odd ? row0 + 8 : row0;      // == t index
            #pragma unroll
            for (int n8 = 0; n8 < 8; ++n8) {
                int col = wn + n8 * 8 + c2;         // local col (0..127)
                int qb = col & ~3;
                int hloc = qb >> 2;                 // 0..31
                int hidx = (n0 >> 2) + hloc;        // global hidden index
                float v0 = __shfl_xor_sync(0xffffffffu, c[mi][n8][0], 1);
                float v1 = __shfl_xor_sync(0xffffffffu, c[mi][n8][1], 1);
                float v2 = __shfl_xor_sync(0xffffffffu, c[mi][n8][2], 1);
                float v3 = __shfl_xor_sync(0xffffffffu, c[mi][n8][3], 1);
                float iv, fv, gv, ov;
                if (!odd) { iv = c[mi][n8][0]; fv = c[mi][n8][1]; gv = v0; ov = v1; }
                else      { iv = v2; fv = v3; gv = c[mi][n8][2]; ov = c[mi][n8][3]; }
                float4 hbq = *reinterpret_cast<const float4*>(hb + b * G4_ + n0 + qb);
                iv += hbq.x; fv += hbq.y; gv += hbq.z; ov += hbq.w;
                float c0v = c0in[b * H_ + hidx];
                float cn = sigf(fv) * c0v + sigf(iv) * tanhf(gv);
                float hn = sigf(ov) * tanhf(cn);
                *reinterpret_cast<__half*>(smem + SM0 + (myrow * HROW + hloc) * 2) =
                    __float2half(hn);
                if (myrow == T_ - 1) {
                    outh[b * H_ + hidx] = hn;
                    outc[b * H_ + hidx] = cn;
                }
            }
        }
        __syncthreads();
        // coalesced copy: 128 rows x 32 half (64B/row) as uint4
        int row = tid >> 2;              // 0..63
        int ch  = tid & 3;               // 16B chunk within row
        #pragma unroll
        for (int rr = 0; rr < 2; ++rr) {
            int r = row + rr * 64;
            uint4 v = *reinterpret_cast<uint4*>(smem + SM0 + r * (HROW * 2) + ch * 16);
            *reinterpret_cast<uint4*>(Aout + (size_t)(m0 + r) * H_ + (n0 >> 2) + ch * 8) = v;
        }
    }
}

// ---------------------------------------------------------------------------
// embed + relu -> fp16 A0 [M, H]
// ---------------------------------------------------------------------------
__global__ void embed_half_kernel(const int* __restrict__ tgt,
                                  const float* __restrict__ emb) {
    int idx = blockIdx.x * 256 + threadIdx.x;   // over M_*H_/4
    int m = idx >> 7;          // H_/4 = 128 float4 per row
    int q = idx & 127;
    int b = m >> 7, t = m & 127;
    int tok = (t == 0) ? 1 : tgt[b * T_ + t - 1];
    float4 v = reinterpret_cast<const float4*>(emb + (size_t)tok * H_)[q];
    __half2* dst = reinterpret_cast<__half2*>(g_A0) + idx * 2;
    dst[0] = __floats2half2_rn(fmaxf(v.x, 0.f), fmaxf(v.y, 0.f));
    dst[1] = __floats2half2_rn(fmaxf(v.z, 0.f), fmaxf(v.w, 0.f));
}

// ---------------------------------------------------------------------------
// W_ih permuted convert: row n = W[(n&3)*H + (n>>2)], fp32->fp16 into g_Whf
// ---------------------------------------------------------------------------
__global__ void wconv_perm_kernel(const float* __restrict__ W) {
    int idx = blockIdx.x * 256 + threadIdx.x;   // over G4_*(H_/4)
    int n = idx >> 7;
    int k4 = idx & 127;
    const float4 v = reinterpret_cast<const float4*>(
        W + (size_t)(((n & 3) << 9) | (n >> 2)) * H_)[k4];
    __half2* dst = reinterpret_cast<__half2*>(g_Whf) + ((size_t)n * (H_ / 2) + k4 * 2);
    dst[0] = __floats2half2_rn(v.x, v.y);
    dst[1] = __floats2half2_rn(v.z, v.w);
}

// ---------------------------------------------------------------------------
// W_out fp32 -> fp16 into g_Wout (runs on a side stream, overlapped)
// ---------------------------------------------------------------------------
__global__ void wconv_out_kernel(const float* __restrict__ W, int total4) {
    int idx = blockIdx.x * 256 + threadIdx.x;
    if (idx >= total4) return;
    float4 v = reinterpret_cast<const float4*>(W)[idx];
    __half2* dst = reinterpret_cast<__half2*>(g_Wout) + idx * 2;
    dst[0] = __floats2half2_rn(v.x, v.y);
    dst[1] = __floats2half2_rn(v.z, v.w);
}

// ---------------------------------------------------------------------------
// hb'[b][(h<<2)|gate] = dot(h0[b,:], W_hh[gate*H+h,:]) + b_ih[g] + b_hh[g]
// ---------------------------------------------------------------------------
__global__ void hb_kernel(const float* __restrict__ h0,
                          const float* __restrict__ Whh,
                          const float* __restrict__ bih,
                          const float* __restrict__ bhh) {
    int g = blockIdx.x * 8 + threadIdx.y;     // original gate-row index
    int b = blockIdx.y;
    const float4* hr = reinterpret_cast<const float4*>(h0 + (size_t)b * H_);
    const float4* wr = reinterpret_cast<const float4*>(Whh + (size_t)g * H_);
    float s = 0.f;
    for (int k = threadIdx.x; k < H_ / 4; k += 32) {
        float4 a = hr[k], w = wr[k];
        s += a.x * w.x + a.y * w.y + a.z * w.z + a.w * w.w;
    }
    #pragma unroll
    for (int o = 16; o; o >>= 1) s += __shfl_xor_sync(0xffffffffu, s, o);
    if (threadIdx.x == 0) {
        int n = ((g & 511) << 2) | (g >> 9);   // permuted column index
        g_hb[b * G4_ + n] = s + bih[g] + bhh[g];
    }
}

// ---------------------------------------------------------------------------
typedef CUresult (*PFN_tmapEnc)(CUtensorMap*, CUtensorMapDataType, unsigned int, void*,
                                const unsigned long long*, const unsigned long long*,
                                const unsigned int*, const unsigned int*,
                                CUtensorMapInterleave, CUtensorMapSwizzle,
                                CUtensorMapL2promotion, CUtensorMapFloatOOBfill);

static void make_map(CUtensorMap* m, void* base, unsigned long long rows, PFN_tmapEnc enc) {
    unsigned long long dims[2] = { (unsigned long long)H_, rows };
    unsigned long long str[1]  = { (unsigned long long)H_ * 2 };
    unsigned int box[2] = { (unsigned int)BK_, (unsigned int)BM_ };
    unsigned int es[2]  = { 1u, 1u };
    enc(m, CU_TENSOR_MAP_DATA_TYPE_FLOAT16, 2, base, dims, str, box, es,
        CU_TENSOR_MAP_INTERLEAVE_NONE, CU_TENSOR_MAP_SWIZZLE_128B,
        CU_TENSOR_MAP_L2_PROMOTION_L2_128B, CU_TENSOR_MAP_FLOAT_OOB_FILL_NONE);
}

extern "C" void kernel_launch(void* const* d_in, const int* in_sizes, int n_in,
                              void* d_out, int out_size) {
    const float* enc_h = (const float*)d_in[1];
    const float* enc_c = (const float*)d_in[2];
    const int*   tgt   = (const int*)  d_in[3];
    const float* emb   = (const float*)d_in[4];
    const float* W_ih  = (const float*)d_in[5];
    const float* W_hh  = (const float*)d_in[6];
    const float* b_ih  = (const float*)d_in[7];
    const float* b_hh  = (const float*)d_in[8];
    const float* W_out = (const float*)d_in[9];
    const float* b_out = (const float*)d_in[10];
    float* out = (float*)d_out;

    static bool inited = false;
    static float* hbp = nullptr;
    static float* dummy = nullptr;
    static __half *A0 = nullptr, *A1 = nullptr;
    static CUtensorMap mapA0, mapA1, mapB, mapBo;
    static cudaStream_t s2;
    static cudaEvent_t e1, e2;
    if (!inited) {
        void* p;
        cudaGetSymbolAddress(&p, g_hb);    hbp   = (float*)p;
        cudaGetSymbolAddress(&p, g_dummy); dummy = (float*)p;
        cudaGetSymbolAddress(&p, g_A0);    A0    = (__half*)p;
        cudaGetSymbolAddress(&p, g_A1);    A1    = (__half*)p;
        void* pW;  cudaGetSymbolAddress(&pW,  g_Whf);
        void* pWo; cudaGetSymbolAddress(&pWo, g_Wout);

        void* fn = nullptr;
        cudaDriverEntryPointQueryResult qr;
        cudaGetDriverEntryPoint("cuTensorMapEncodeTiled", &fn, cudaEnableDefault, &qr);
        PFN_tmapEnc enc = (PFN_tmapEnc)fn;
        make_map(&mapA0, A0,  M_, enc);
        make_map(&mapA1, A1,  M_, enc);
        make_map(&mapB,  pW,  G4_, enc);
        make_map(&mapBo, pWo, V_, enc);

        cudaFuncSetAttribute(gemm_f16, cudaFuncAttributeMaxDynamicSharedMemorySize, SMEM_TOTAL);
        cudaStreamCreateWithFlags(&s2, cudaStreamNonBlocking);
        cudaEventCreateWithFlags(&e1, cudaEventDisableTiming);
        cudaEventCreateWithFlags(&e2, cudaEventDisableTiming);
        inited = true;
    }

    // output layout: [logits (M_*V_), h_last (L,B,H), c_last (L,B,H)]
    const long long need = (long long)M_ * V_ + 2LL * L_ * B_ * H_;
    float *hl, *cl;
    if ((long long)out_size >= need) {
        hl = out + (size_t)M_ * V_;
        cl = hl + (size_t)L_ * B_ * H_;
    } else {
        hl = dummy;
        cl = dummy + (size_t)L_ * B_ * H_;
    }

    // Fork: W_out conversion runs on side stream, overlapped with LSTM phase.
    cudaEventRecord(e1, 0);
    cudaStreamWaitEvent(s2, e1, 0);
    wconv_out_kernel<<<((V_ * H_ / 4) + 255) / 256, 256, 0, s2>>>(W_out, V_ * H_ / 4);
    cudaEventRecord(e2, s2);

    // 1. embedding + relu (fp16 A0)
    embed_half_kernel<<<(M_ * H_ / 4) / 256, 256>>>(tgt, emb);

    // 2. two LSTM layers: gates GEMM with fused LSTM epilogue (A ping-pong)
    for (int l = 0; l < L_; ++l) {
        hb_kernel<<<dim3(G4_ / 8, B_), dim3(32, 8)>>>(
            enc_h + (size_t)l * B_ * H_, W_hh + (size_t)l * G4_ * H_,
            b_ih + (size_t)l * G4_, b_hh + (size_t)l * G4_);
        wconv_perm_kernel<<<(G4_ * H_ / 4) / 256, 256>>>(W_ih + (size_t)l * G4_ * H_);
        gemm_f16<<<dim3(M_ / BM_, G4_ / BN_), NTHR, SMEM_TOTAL>>>(
            (l == 0) ? mapA0 : mapA1, mapB,
            nullptr, 0, nullptr, /*mode=*/1,
            hbp, enc_c + (size_t)l * B_ * H_,
            (l == 0) ? A1 : A0,
            hl + (size_t)l * B_ * H_, cl + (size_t)l * B_ * H_);
    }

    // Join: logits GEMM needs g_Wout.
    cudaStreamWaitEvent(0, e2, 0);

    // 3. output projection: logits = X2 * W_out^T + b_out  (X2 is in A0)
    gemm_f16<<<dim3(M_ / BM_, V_ / BN_), NTHR, SMEM_TOTAL>>>(
        mapA0, mapBo, out, V_, b_out, /*mode=*/0,
        nullptr, nullptr, nullptr, nullptr, nullptr);
}

// round 10
// speedup vs baseline: 1.4631x; 1.4631x over previous
#include <cuda_runtime.h>
#include <cuda_fp16.h>
#include <cuda.h>
#include <cstdint>

// ---------------- problem constants ----------------
#define B_    16
#define T_    128
#define H_    512
#define L_    2
#define V_    32000
#define M_    (B_ * T_)        // 2048
#define G4_   (4 * H_)         // 2048

// ---------------- GEMM tiling ----------------
#define BM_   128
#define BN_   128
#define BK_   64               // fp16 = 128 bytes/row = SW128 atom
#define KT_   (H_ / BK_)       // 8 k-tiles
#define NSTG  3
#define ST_A  (BM_ * BK_ * 2)  // 16384
#define ST_B  (BN_ * BK_ * 2)  // 16384
#define ST_BYTES (ST_A + ST_B) // 32768
#define SM0   1024
#define SMEM_TOTAL (SM0 + NSTG * ST_BYTES)   // 99328 -> 2 CTAs/SM
#define NTHR  256              // 8 warps: 4 m-warps x 2 n-warps, warp tile 32x64
#define NWARP (NTHR / 32)

// h-tile staging: 128 rows x 32 half, row stride 40 half (80B, conflict-free)
#define HROW  40

// ---------------- scratch (static device globals) ----------------
__device__ __align__(128) __half g_A0[(size_t)M_ * H_];    // activations ping
__device__ __align__(128) __half g_A1[(size_t)M_ * H_];    // activations pong
__device__ __align__(128) __half g_Whf[(size_t)G4_ * H_];  // fp16 W_ih (permuted)
__device__ __align__(128) __half g_Wout[(size_t)V_ * H_];  // fp16 W_out
__device__ float g_hb[B_ * G4_];                           // permuted recurrent contribution
__device__ float g_dummy[2 * L_ * B_ * H_];

__device__ __forceinline__ float sigf(float x) { return 1.0f / (1.0f + expf(-x)); }

// ---------------- PTX helpers (base ISA only; no tcgen05 on sm_103 target) ----
__device__ __forceinline__ uint32_t smem_u32(const void* p) {
    uint32_t a;
    asm("{ .reg .u64 t; cvta.to.shared.u64 t, %1; cvt.u32.u64 %0, t; }" : "=r"(a) : "l"(p));
    return a;
}
__device__ __forceinline__ bool elect1() {
    uint32_t p;
    asm volatile("{ .reg .pred p; elect.sync _|p, 0xFFFFFFFF; selp.b32 %0, 1, 0, p; }" : "=r"(p));
    return p != 0;
}
__device__ __forceinline__ void mbar_init(uint32_t a, uint32_t c) {
    asm volatile("mbarrier.init.shared.b64 [%0], %1;" :: "r"(a), "r"(c) : "memory");
}
__device__ __forceinline__ void mbar_arrive(uint32_t a) {
    asm volatile("mbarrier.arrive.shared.b64 _, [%0];" :: "r"(a) : "memory");
}
__device__ __forceinline__ void mbar_expect_tx(uint32_t a, uint32_t b) {
    asm volatile("mbarrier.arrive.expect_tx.shared.b64 _, [%0], %1;" :: "r"(a), "r"(b) : "memory");
}
__device__ __forceinline__ void mbar_wait(uint32_t a, uint32_t ph) {
    asm volatile(
        "{ .reg .pred P;\n"
        "WL_%=: mbarrier.try_wait.parity.acquire.cta.shared::cta.b64 P, [%0], %1, 0x989680;\n"
        "@P bra.uni WD_%=;\n"
        "bra.uni WL_%=;\n"
        "WD_%=: }" :: "r"(a), "r"(ph) : "memory");
}
__device__ __forceinline__ void tma2d(uint32_t dst, const CUtensorMap* m, int x, int y, uint32_t mbar) {
    asm volatile(
        "cp.async.bulk.tensor.2d.shared::cta.global.tile.mbarrier::complete_tx::bytes "
        "[%0], [%1, {%2, %3}], [%4];"
        :: "r"(dst), "l"(m), "r"(x), "r"(y), "r"(mbar) : "memory");
}
__device__ __forceinline__ void ldsm4(uint32_t& r0, uint32_t& r1, uint32_t& r2, uint32_t& r3,
                                      uint32_t addr) {
    asm volatile("ldmatrix.sync.aligned.m8n8.x4.shared.b16 {%0,%1,%2,%3}, [%4];"
                 : "=r"(r0), "=r"(r1), "=r"(r2), "=r"(r3) : "r"(addr));
}
__device__ __forceinline__ void mma16816(float* c, const uint32_t* a, uint32_t b0, uint32_t b1) {
    asm volatile(
        "mma.sync.aligned.m16n8k16.row.col.f32.f16.f16.f32 "
        "{%0,%1,%2,%3}, {%4,%5,%6,%7}, {%8,%9}, {%0,%1,%2,%3};"
        : "+f"(c[0]), "+f"(c[1]), "+f"(c[2]), "+f"(c[3])
        : "r"(a[0]), "r"(a[1]), "r"(a[2]), "r"(a[3]), "r"(b0), "r"(b1));
}

// ---------------------------------------------------------------------------
// fp16 GEMM with two epilogue modes:
//   mode 0: C[m,n] = acc + bias[n]            (fp32 output, logits)
//   mode 1: fused LSTM cell on permuted-gate columns; h staged through smem
//           (conflict-free stride) then written coalesced into Aout.
// CTA tile 128x128, 256 threads (8 warps, 4m x 2n, warp tile 32x64),
// 2 CTAs/SM, async mbarrier pipeline (no __syncthreads in mainloop).
// ---------------------------------------------------------------------------
__global__ __launch_bounds__(NTHR, 2)
void gemm_f16(const __grid_constant__ CUtensorMap mapA,
              const __grid_constant__ CUtensorMap mapB,
              float* __restrict__ C, int ldc,
              const float* __restrict__ bias,
              int mode,
              const float* __restrict__ hb,
              const float* __restrict__ c0in,
              __half* __restrict__ Aout,
              float* __restrict__ outh,
              float* __restrict__ outc) {
    extern __shared__ __align__(1024) char smem[];
    const uint32_t sb = smem_u32(smem);
    const int tid = threadIdx.x, wid = tid >> 5, lane = tid & 31;
    const int m0 = blockIdx.x * BM_;
    const int n0 = blockIdx.y * BN_;
    const int wm = (wid & 3) * 32;        // warp m offset in CTA tile
    const int wn = (wid >> 2) * 64;       // warp n offset in CTA tile

    const uint32_t FULL  = sb;                // NSTG x 8B
    const uint32_t EMPTY = sb + 8 * NSTG;     // NSTG x 8B

    if (tid == 0) {
        #pragma unroll
        for (int s = 0; s < NSTG; ++s) {
            mbar_init(FULL + 8 * s, 1);
            mbar_init(EMPTY + 8 * s, NWARP);
        }
    }
    __syncthreads();

    if (tid == 0) {
        #pragma unroll
        for (int s = 0; s < NSTG; ++s) {
            mbar_expect_tx(FULL + 8 * s, ST_BYTES);
            uint32_t sa = sb + SM0 + s * ST_BYTES;
            tma2d(sa,        &mapA, s * BK_, m0, FULL + 8 * s);
            tma2d(sa + ST_A, &mapB, s * BK_, n0, FULL + 8 * s);
        }
    }

    float c[2][8][4];
    #pragma unroll
    for (int mi = 0; mi < 2; ++mi)
        #pragma unroll
        for (int nj = 0; nj < 8; ++nj)
            #pragma unroll
            for (int q = 0; q < 4; ++q) c[mi][nj][q] = 0.f;

    const int lr = lane & 15;     // ldmatrix row within 16
    const int hi = lane >> 4;     // ldmatrix k-chunk select

    uint32_t offA[2], offB[4];
    #pragma unroll
    for (int mi = 0; mi < 2; ++mi) {
        int r = wm + mi * 16 + lr;
        offA[mi] = (uint32_t)(r * 128 + ((hi ^ (r & 7)) << 4));
    }
    #pragma unroll
    for (int nj = 0; nj < 4; ++nj) {
        int r = wn + nj * 16 + lr;
        offB[nj] = (uint32_t)(ST_A + r * 128 + ((hi ^ (r & 7)) << 4));
    }

    const bool producer = (wid == 0) && elect1();

    for (int kt = 0; kt < KT_; ++kt) {
        const int s = kt % NSTG;
        mbar_wait(FULL + 8 * s, (kt / NSTG) & 1);
        const uint32_t sa = sb + SM0 + s * ST_BYTES;

        #pragma unroll
        for (int kk = 0; kk < 4; ++kk) {
            const uint32_t kx = (uint32_t)(kk << 5);
            uint32_t am[2][4], bt[4][4];
            #pragma unroll
            for (int mi = 0; mi < 2; ++mi)
                ldsm4(am[mi][0], am[mi][1], am[mi][2], am[mi][3], sa + (offA[mi] ^ kx));
            #pragma unroll
            for (int nj = 0; nj < 4; ++nj)
                ldsm4(bt[nj][0], bt[nj][1], bt[nj][2], bt[nj][3], sa + (offB[nj] ^ kx));
            #pragma unroll
            for (int mi = 0; mi < 2; ++mi)
                #pragma unroll
                for (int n8 = 0; n8 < 8; ++n8)
                    mma16816(c[mi][n8], am[mi],
                             bt[n8 >> 1][n8 & 1], bt[n8 >> 1][(n8 & 1) + 2]);
        }

        if (lane == 0) mbar_arrive(EMPTY + 8 * s);

        if (producer && kt + NSTG < KT_) {
            mbar_wait(EMPTY + 8 * s, (kt / NSTG) & 1);
            mbar_expect_tx(FULL + 8 * s, ST_BYTES);
            uint32_t sn = sb + SM0 + s * ST_BYTES;
            tma2d(sn,        &mapA, (kt + NSTG) * BK_, m0, FULL + 8 * s);
            tma2d(sn + ST_A, &mapB, (kt + NSTG) * BK_, n0, FULL + 8 * s);
        }
    }

    const int r4 = lane >> 2;            // accum row within 8
    const int c2 = (lane & 3) << 1;      // accum col pair

    if (mode == 0) {
        // -------- logits epilogue: direct register -> global stores --------
        #pragma unroll
        for (int mi = 0; mi < 2; ++mi) {
            int row0 = m0 + wm + mi * 16 + r4;
            #pragma unroll
            for (int n8 = 0; n8 < 8; ++n8) {
                int col = n0 + wn + n8 * 8 + c2;
                float bx = bias[col], by = bias[col + 1];
                float2 v0 = { c[mi][n8][0] + bx, c[mi][n8][1] + by };
                float2 v1 = { c[mi][n8][2] + bx, c[mi][n8][3] + by };
                *reinterpret_cast<float2*>(C + (size_t)row0 * ldc + col) = v0;
                *reinterpret_cast<float2*>(C + (size_t)(row0 + 8) * ldc + col) = v1;
            }
        }
    } else {
        // -------- fused LSTM epilogue, smem-staged coalesced writes --------
        // Even lanes hold (i,f) of their col-quad; odd lanes hold (g,o).
        // shfl_xor(1) swaps; even lane computes local row0, odd lane row0+8.
        const int b = m0 >> 7;            // BM_ == T_ so batch fixed per CTA
        const bool odd = lane & 1;
        __syncthreads();                  // all warps done with pipeline smem
        #pragma unroll
        for (int mi = 0; mi < 2; ++mi) {
            int row0 = wm + mi * 16 + r4;           // local row
            int myrow = odd ? row0 + 8 : row0;      // == t index
            #pragma unroll
            for (int n8 = 0; n8 < 8; ++n8) {
                int col = wn + n8 * 8 + c2;         // local col (0..127)
                int qb = col & ~3;
                int hloc = qb >> 2;                 // 0..31
                int hidx = (n0 >> 2) + hloc;        // global hidden index
                float v0 = __shfl_xor_sync(0xffffffffu, c[mi][n8][0], 1);
                float v1 = __shfl_xor_sync(0xffffffffu, c[mi][n8][1], 1);
                float v2 = __shfl_xor_sync(0xffffffffu, c[mi][n8][2], 1);
                float v3 = __shfl_xor_sync(0xffffffffu, c[mi][n8][3], 1);
                float iv, fv, gv, ov;
                if (!odd) { iv = c[mi][n8][0]; fv = c[mi][n8][1]; gv = v0; ov = v1; }
                else      { iv = v2; fv = v3; gv = c[mi][n8][2]; ov = c[mi][n8][3]; }
                float4 hbq = *reinterpret_cast<const float4*>(hb + b * G4_ + n0 + qb);
                iv += hbq.x; fv += hbq.y; gv += hbq.z; ov += hbq.w;
                float c0v = c0in[b * H_ + hidx];
                float cn = sigf(fv) * c0v + sigf(iv) * tanhf(gv);
                float hn = sigf(ov) * tanhf(cn);
                *reinterpret_cast<__half*>(smem + SM0 + (myrow * HROW + hloc) * 2) =
                    __float2half(hn);
                if (myrow == T_ - 1) {
                    outh[b * H_ + hidx] = hn;
                    outc[b * H_ + hidx] = cn;
                }
            }
        }
        __syncthreads();
        // coalesced copy: 128 rows x 32 half (64B/row) as uint4
        int row = tid >> 2;              // 0..63
        int ch  = tid & 3;               // 16B chunk within row
        #pragma unroll
        for (int rr = 0; rr < 2; ++rr) {
            int r = row + rr * 64;
            uint4 v = *reinterpret_cast<uint4*>(smem + SM0 + r * (HROW * 2) + ch * 16);
            *reinterpret_cast<uint4*>(Aout + (size_t)(m0 + r) * H_ + (n0 >> 2) + ch * 8) = v;
        }
    }
}

// ---------------------------------------------------------------------------
// embed + relu -> fp16 A0 [M, H]
// ---------------------------------------------------------------------------
__global__ void embed_half_kernel(const int* __restrict__ tgt,
                                  const float* __restrict__ emb) {
    int idx = blockIdx.x * 256 + threadIdx.x;   // over M_*H_/4
    int m = idx >> 7;          // H_/4 = 128 float4 per row
    int q = idx & 127;
    int b = m >> 7, t = m & 127;
    int tok = (t == 0) ? 1 : tgt[b * T_ + t - 1];
    float4 v = reinterpret_cast<const float4*>(emb + (size_t)tok * H_)[q];
    __half2* dst = reinterpret_cast<__half2*>(g_A0) + idx * 2;
    dst[0] = __floats2half2_rn(fmaxf(v.x, 0.f), fmaxf(v.y, 0.f));
    dst[1] = __floats2half2_rn(fmaxf(v.z, 0.f), fmaxf(v.w, 0.f));
}

// ---------------------------------------------------------------------------
// W_ih permuted convert: row n = W[(n&3)*H + (n>>2)], fp32->fp16 into g_Whf
// ---------------------------------------------------------------------------
__global__ void wconv_perm_kernel(const float* __restrict__ W) {
    int idx = blockIdx.x * 256 + threadIdx.x;   // over G4_*(H_/4)
    int n = idx >> 7;
    int k4 = idx & 127;
    const float4 v = reinterpret_cast<const float4*>(
        W + (size_t)(((n & 3) << 9) | (n >> 2)) * H_)[k4];
    __half2* dst = reinterpret_cast<__half2*>(g_Whf) + ((size_t)n * (H_ / 2) + k4 * 2);
    dst[0] = __floats2half2_rn(v.x, v.y);
    dst[1] = __floats2half2_rn(v.z, v.w);
}

// ---------------------------------------------------------------------------
// W_out fp32 -> fp16 into g_Wout (runs on a side stream, overlapped)
// ---------------------------------------------------------------------------
__global__ void wconv_out_kernel(const float* __restrict__ W, int total4) {
    int idx = blockIdx.x * 256 + threadIdx.x;
    if (idx >= total4) return;
    float4 v = reinterpret_cast<const float4*>(W)[idx];
    __half2* dst = reinterpret_cast<__half2*>(g_Wout) + idx * 2;
    dst[0] = __floats2half2_rn(v.x, v.y);
    dst[1] = __floats2half2_rn(v.z, v.w);
}

// ---------------------------------------------------------------------------
// hb'[b][(h<<2)|gate] = dot(h0[b,:], W_hh[gate*H+h,:]) + b_ih[g] + b_hh[g]
// ---------------------------------------------------------------------------
__global__ void hb_kernel(const float* __restrict__ h0,
                          const float* __restrict__ Whh,
                          const float* __restrict__ bih,
                          const float* __restrict__ bhh) {
    int g = blockIdx.x * 8 + threadIdx.y;     // original gate-row index
    int b = blockIdx.y;
    const float4* hr = reinterpret_cast<const float4*>(h0 + (size_t)b * H_);
    const float4* wr = reinterpret_cast<const float4*>(Whh + (size_t)g * H_);
    float s = 0.f;
    for (int k = threadIdx.x; k < H_ / 4; k += 32) {
        float4 a = hr[k], w = wr[k];
        s += a.x * w.x + a.y * w.y + a.z * w.z + a.w * w.w;
    }
    #pragma unroll
    for (int o = 16; o; o >>= 1) s += __shfl_xor_sync(0xffffffffu, s, o);
    if (threadIdx.x == 0) {
        int n = ((g & 511) << 2) | (g >> 9);   // permuted column index
        g_hb[b * G4_ + n] = s + bih[g] + bhh[g];
    }
}

// ---------------------------------------------------------------------------
typedef CUresult (*PFN_tmapEnc)(CUtensorMap*, CUtensorMapDataType, unsigned int, void*,
                                const unsigned long long*, const unsigned long long*,
                                const unsigned int*, const unsigned int*,
                                CUtensorMapInterleave, CUtensorMapSwizzle,
                                CUtensorMapL2promotion, CUtensorMapFloatOOBfill);

static void make_map(CUtensorMap* m, void* base, unsigned long long rows, PFN_tmapEnc enc) {
    unsigned long long dims[2] = { (unsigned long long)H_, rows };
    unsigned long long str[1]  = { (unsigned long long)H_ * 2 };
    unsigned int box[2] = { (unsigned int)BK_, (unsigned int)BM_ };
    unsigned int es[2]  = { 1u, 1u };
    enc(m, CU_TENSOR_MAP_DATA_TYPE_FLOAT16, 2, base, dims, str, box, es,
        CU_TENSOR_MAP_INTERLEAVE_NONE, CU_TENSOR_MAP_SWIZZLE_128B,
        CU_TENSOR_MAP_L2_PROMOTION_L2_128B, CU_TENSOR_MAP_FLOAT_OOB_FILL_NONE);
}

extern "C" void kernel_launch(void* const* d_in, const int* in_sizes, int n_in,
                              void* d_out, int out_size) {
    const float* enc_h = (const float*)d_in[1];
    const float* enc_c = (const float*)d_in[2];
    const int*   tgt   = (const int*)  d_in[3];
    const float* emb   = (const float*)d_in[4];
    const float* W_ih  = (const float*)d_in[5];
    const float* W_hh  = (const float*)d_in[6];
    const float* b_ih  = (const float*)d_in[7];
    const float* b_hh  = (const float*)d_in[8];
    const float* W_out = (const float*)d_in[9];
    const float* b_out = (const float*)d_in[10];
    float* out = (float*)d_out;

    static bool inited = false;
    static float* hbp = nullptr;
    static float* dummy = nullptr;
    static __half *A0 = nullptr, *A1 = nullptr;
    static CUtensorMap mapA0, mapA1, mapB, mapBo;
    static cudaStream_t s2;
    static cudaEvent_t e1, e2;
    if (!inited) {
        void* p;
        cudaGetSymbolAddress(&p, g_hb);    hbp   = (float*)p;
        cudaGetSymbolAddress(&p, g_dummy); dummy = (float*)p;
        cudaGetSymbolAddress(&p, g_A0);    A0    = (__half*)p;
        cudaGetSymbolAddress(&p, g_A1);    A1    = (__half*)p;
        void* pW;  cudaGetSymbolAddress(&pW,  g_Whf);
        void* pWo; cudaGetSymbolAddress(&pWo, g_Wout);

        void* fn = nullptr;
        cudaDriverEntryPointQueryResult qr;
        cudaGetDriverEntryPoint("cuTensorMapEncodeTiled", &fn, cudaEnableDefault, &qr);
        PFN_tmapEnc enc = (PFN_tmapEnc)fn;
        make_map(&mapA0, A0,  M_, enc);
        make_map(&mapA1, A1,  M_, enc);
        make_map(&mapB,  pW,  G4_, enc);
        make_map(&mapBo, pWo, V_, enc);

        cudaFuncSetAttribute(gemm_f16, cudaFuncAttributeMaxDynamicSharedMemorySize, SMEM_TOTAL);
        cudaStreamCreateWithFlags(&s2, cudaStreamNonBlocking);
        cudaEventCreateWithFlags(&e1, cudaEventDisableTiming);
        cudaEventCreateWithFlags(&e2, cudaEventDisableTiming);
        inited = true;
    }

    // output layout: [logits (M_*V_), h_last (L,B,H), c_last (L,B,H)]
    const long long need = (long long)M_ * V_ + 2LL * L_ * B_ * H_;
    float *hl, *cl;
    if ((long long)out_size >= need) {
        hl = out + (size_t)M_ * V_;
        cl = hl + (size_t)L_ * B_ * H_;
    } else {
        hl = dummy;
        cl = dummy + (size_t)L_ * B_ * H_;
    }

    // Fork: W_out conversion runs on side stream, overlapped with LSTM phase.
    cudaEventRecord(e1, 0);
    cudaStreamWaitEvent(s2, e1, 0);
    wconv_out_kernel<<<((V_ * H_ / 4) + 255) / 256, 256, 0, s2>>>(W_out, V_ * H_ / 4);
    cudaEventRecord(e2, s2);

    // 1. embedding + relu (fp16 A0)
    embed_half_kernel<<<(M_ * H_ / 4) / 256, 256>>>(tgt, emb);

    // 2. two LSTM layers: gates GEMM with fused LSTM epilogue (A ping-pong)
    for (int l = 0; l < L_; ++l) {
        hb_kernel<<<dim3(G4_ / 8, B_), dim3(32, 8)>>>(
            enc_h + (size_t)l * B_ * H_, W_hh + (size_t)l * G4_ * H_,
            b_ih + (size_t)l * G4_, b_hh + (size_t)l * G4_);
        wconv_perm_kernel<<<(G4_ * H_ / 4) / 256, 256>>>(W_ih + (size_t)l * G4_ * H_);
        gemm_f16<<<dim3(M_ / BM_, G4_ / BN_), NTHR, SMEM_TOTAL>>>(
            (l == 0) ? mapA0 : mapA1, mapB,
            nullptr, 0, nullptr, /*mode=*/1,
            hbp, enc_c + (size_t)l * B_ * H_,
            (l == 0) ? A1 : A0,
            hl + (size_t)l * B_ * H_, cl + (size_t)l * B_ * H_);
    }

    // Join: logits GEMM needs g_Wout.
    cudaStreamWaitEvent(0, e2, 0);

    // 3. output projection: logits = X2 * W_out^T + b_out  (X2 is in A0)
    gemm_f16<<<dim3(M_ / BM_, V_ / BN_), NTHR, SMEM_TOTAL>>>(
        mapA0, mapBo, out, V_, b_out, /*mode=*/0,
        nullptr, nullptr, nullptr, nullptr, nullptr);
}